// round 1
// baseline (speedup 1.0000x reference)
#include <cuda_runtime.h>
#include <cuda_bf16.h>
#include <math.h>

// ---------------- problem constants ----------------
#define BB   2
#define TT   1024
#define DD   768
#define HH   12
#define HDIM 64
#define LL   4
#define VV   50257
#define MM   (BB*TT)      // 2048 rows
#define D3   (3*DD)       // 2304
#define D4   (4*DD)       // 3072

// ---------------- scratch (device globals; no allocations allowed) ----------
__device__ float g_x   [MM * DD];   // residual stream
__device__ float g_h   [MM * DD];   // layernorm output
__device__ float g_qkv [MM * D3];   // qkv projection
__device__ float g_attn[MM * DD];   // attention output
__device__ float g_fc  [MM * D4];   // mlp hidden

// ---------------- embedding ----------------
__global__ void embed_kernel(const int* __restrict__ ids,
                             const float* __restrict__ wte,
                             const float* __restrict__ wpe,
                             float* __restrict__ x) {
    int idx = blockIdx.x * blockDim.x + threadIdx.x;
    if (idx >= MM * DD) return;
    int d  = idx % DD;
    int bt = idx / DD;
    int t  = bt % TT;
    x[idx] = wte[(size_t)ids[bt] * DD + d] + wpe[(size_t)t * DD + d];
}

// ---------------- layernorm (one block per row) ----------------
__global__ void layernorm_kernel(const float* __restrict__ x,
                                 const float* __restrict__ g,
                                 const float* __restrict__ b,
                                 float* __restrict__ out, int D) {
    int row = blockIdx.x;
    int tid = threadIdx.x;
    __shared__ float red[256];
    __shared__ float s_mu, s_rstd;
    const float* xr = x + (size_t)row * D;

    float s = 0.f;
    for (int d = tid; d < D; d += 256) s += xr[d];
    red[tid] = s; __syncthreads();
    for (int o = 128; o > 0; o >>= 1) {
        if (tid < o) red[tid] += red[tid + o];
        __syncthreads();
    }
    if (tid == 0) s_mu = red[0] / D;
    __syncthreads();
    float mu = s_mu;

    float v = 0.f;
    for (int d = tid; d < D; d += 256) { float t = xr[d] - mu; v += t * t; }
    red[tid] = v; __syncthreads();
    for (int o = 128; o > 0; o >>= 1) {
        if (tid < o) red[tid] += red[tid + o];
        __syncthreads();
    }
    if (tid == 0) s_rstd = rsqrtf(red[0] / D + 1e-5f);
    __syncthreads();
    float rstd = s_rstd;

    float* orow = out + (size_t)row * D;
    for (int d = tid; d < D; d += 256)
        orow[d] = g[d] * (xr[d] - mu) * rstd + b[d];
}

// ---------------- tiled fp32 GEMM ----------------
// C[M,N] = A[M,K] @ B + bias (+gelu) (+residual)
// TRANS_B==0: B is [K,N] row-major.  TRANS_B==1: B is [N,K] row-major.
// BM=BN=64, BK=16, blockDim(16,16), 4x4 micro-tile per thread.
template <int TRANS_B, int ACT>
__global__ void gemm_kernel(const float* __restrict__ A,
                            const float* __restrict__ B,
                            const float* __restrict__ bias,
                            const float* __restrict__ residual,
                            float* __restrict__ C,
                            int M, int N, int K) {
    __shared__ float As[64 * 16];   // [m][k]
    __shared__ float Bs[16 * 64];   // [k][n]

    int tx = threadIdx.x, ty = threadIdx.y;
    int tid = ty * 16 + tx;
    int row0 = blockIdx.y * 64;
    int col0 = blockIdx.x * 64;

    float acc[4][4];
#pragma unroll
    for (int i = 0; i < 4; i++)
#pragma unroll
        for (int j = 0; j < 4; j++) acc[i][j] = 0.f;

    for (int kt = 0; kt < K; kt += 16) {
        // load A tile: As[m*16+kk]
#pragma unroll
        for (int i = 0; i < 4; i++) {
            int idx = tid + i * 256;
            int m = idx >> 4, kk = idx & 15;
            int gr = row0 + m, gc = kt + kk;
            As[idx] = (gr < M && gc < K) ? A[(size_t)gr * K + gc] : 0.f;
        }
        // load B tile: Bs[kk*64+n]
        if (TRANS_B == 0) {
#pragma unroll
            for (int i = 0; i < 4; i++) {
                int idx = tid + i * 256;
                int kk = idx >> 6, nn = idx & 63;
                int gr = kt + kk, gc = col0 + nn;
                Bs[idx] = (gr < K && gc < N) ? B[(size_t)gr * N + gc] : 0.f;
            }
        } else {
#pragma unroll
            for (int i = 0; i < 4; i++) {
                int idx = tid + i * 256;
                int nn = idx >> 4, kk = idx & 15;
                int gr = col0 + nn, gc = kt + kk;
                Bs[kk * 64 + nn] = (gr < N && gc < K) ? B[(size_t)gr * K + gc] : 0.f;
            }
        }
        __syncthreads();

#pragma unroll
        for (int kk = 0; kk < 16; kk++) {
            float a0 = As[(ty * 4 + 0) * 16 + kk];
            float a1 = As[(ty * 4 + 1) * 16 + kk];
            float a2 = As[(ty * 4 + 2) * 16 + kk];
            float a3 = As[(ty * 4 + 3) * 16 + kk];
            float4 bv = *reinterpret_cast<const float4*>(&Bs[kk * 64 + tx * 4]);
            acc[0][0] += a0 * bv.x; acc[0][1] += a0 * bv.y; acc[0][2] += a0 * bv.z; acc[0][3] += a0 * bv.w;
            acc[1][0] += a1 * bv.x; acc[1][1] += a1 * bv.y; acc[1][2] += a1 * bv.z; acc[1][3] += a1 * bv.w;
            acc[2][0] += a2 * bv.x; acc[2][1] += a2 * bv.y; acc[2][2] += a2 * bv.z; acc[2][3] += a2 * bv.w;
            acc[3][0] += a3 * bv.x; acc[3][1] += a3 * bv.y; acc[3][2] += a3 * bv.z; acc[3][3] += a3 * bv.w;
        }
        __syncthreads();
    }

#pragma unroll
    for (int i = 0; i < 4; i++) {
        int r = row0 + ty * 4 + i;
        if (r >= M) continue;
#pragma unroll
        for (int j = 0; j < 4; j++) {
            int c = col0 + tx * 4 + j;
            if (c >= N) continue;
            float v = acc[i][j];
            if (bias) v += bias[c];
            if (ACT == 1) v = 0.5f * v * (1.0f + erff(v * 0.70710678118654752f)); // exact GELU
            if (residual) v += residual[(size_t)r * N + c];
            C[(size_t)r * N + c] = v;
        }
    }
}

// ---------------- attention: one block per (q, head, batch) ----------------
__global__ void attention_kernel(const float* __restrict__ qkv,
                                 float* __restrict__ out) {
    int q = blockIdx.x, h = blockIdx.y, b = blockIdx.z;
    int tid = threadIdx.x;
    __shared__ float sq[HDIM];
    __shared__ float ss[TT];
    __shared__ float red[256];

    const float* qptr = qkv + ((size_t)(b * TT + q)) * D3 + h * HDIM;
    if (tid < HDIM) sq[tid] = qptr[tid];
    __syncthreads();

    // scores
    float lmax = -1e30f;
    for (int k = tid; k <= q; k += 256) {
        const float* kptr = qkv + ((size_t)(b * TT + k)) * D3 + DD + h * HDIM;
        float s = 0.f;
#pragma unroll
        for (int d = 0; d < HDIM; d++) s += sq[d] * kptr[d];
        s *= 0.125f;                     // 1/sqrt(64)
        ss[k] = s;
        lmax = fmaxf(lmax, s);
    }
    red[tid] = lmax; __syncthreads();
    for (int o = 128; o > 0; o >>= 1) {
        if (tid < o) red[tid] = fmaxf(red[tid], red[tid + o]);
        __syncthreads();
    }
    float mx = red[0];
    __syncthreads();

    // exp + sum
    float lsum = 0.f;
    for (int k = tid; k <= q; k += 256) {
        float e = expf(ss[k] - mx);
        ss[k] = e;
        lsum += e;
    }
    red[tid] = lsum; __syncthreads();
    for (int o = 128; o > 0; o >>= 1) {
        if (tid < o) red[tid] += red[tid + o];
        __syncthreads();
    }
    float inv = 1.0f / red[0];

    // P @ V : 64 threads, one output dim each
    if (tid < HDIM) {
        const float* vbase = qkv + (size_t)b * TT * D3 + 2 * DD + h * HDIM + tid;
        float acc = 0.f;
        for (int k = 0; k <= q; k++)
            acc += ss[k] * vbase[(size_t)k * D3];
        out[((size_t)(b * TT + q)) * DD + h * HDIM + tid] = acc * inv;
    }
}

// ---------------- launch ----------------
extern "C" void kernel_launch(void* const* d_in, const int* in_sizes, int n_in,
                              void* d_out, int out_size) {
    const int*   ids    = (const int*)  d_in[0];
    const float* wte    = (const float*)d_in[1];
    const float* wpe    = (const float*)d_in[2];
    const float* ln1_g  = (const float*)d_in[3];
    const float* ln1_b  = (const float*)d_in[4];
    const float* attn_w = (const float*)d_in[5];
    const float* attn_b = (const float*)d_in[6];
    const float* proj_w = (const float*)d_in[7];
    const float* proj_b = (const float*)d_in[8];
    const float* ln2_g  = (const float*)d_in[9];
    const float* ln2_b  = (const float*)d_in[10];
    const float* fc_w   = (const float*)d_in[11];
    const float* fc_b   = (const float*)d_in[12];
    const float* out_w  = (const float*)d_in[13];
    const float* out_b  = (const float*)d_in[14];
    const float* lnf_g  = (const float*)d_in[15];
    const float* lnf_b  = (const float*)d_in[16];
    float* logits = (float*)d_out;

    float *x, *h, *qkv, *attn, *fc;
    cudaGetSymbolAddress((void**)&x,    g_x);
    cudaGetSymbolAddress((void**)&h,    g_h);
    cudaGetSymbolAddress((void**)&qkv,  g_qkv);
    cudaGetSymbolAddress((void**)&attn, g_attn);
    cudaGetSymbolAddress((void**)&fc,   g_fc);

    dim3 tpb(16, 16);

    embed_kernel<<<(MM * DD + 255) / 256, 256>>>(ids, wte, wpe, x);

    for (int l = 0; l < LL; l++) {
        // --- attention block ---
        layernorm_kernel<<<MM, 256>>>(x, ln1_g + l * DD, ln1_b + l * DD, h, DD);

        gemm_kernel<0, 0><<<dim3(D3 / 64, MM / 64), tpb>>>(
            h, attn_w + (size_t)l * DD * D3, attn_b + (size_t)l * D3,
            nullptr, qkv, MM, D3, DD);

        attention_kernel<<<dim3(TT, HH, BB), 256>>>(qkv, attn);

        gemm_kernel<0, 0><<<dim3(DD / 64, MM / 64), tpb>>>(
            attn, proj_w + (size_t)l * DD * DD, proj_b + (size_t)l * DD,
            x /*residual*/, x, MM, DD, DD);

        // --- mlp block ---
        layernorm_kernel<<<MM, 256>>>(x, ln2_g + l * DD, ln2_b + l * DD, h, DD);

        gemm_kernel<0, 1><<<dim3(D4 / 64, MM / 64), tpb>>>(
            h, fc_w + (size_t)l * DD * D4, fc_b + (size_t)l * D4,
            nullptr, fc, MM, D4, DD);

        gemm_kernel<0, 0><<<dim3(DD / 64, MM / 64), tpb>>>(
            fc, out_w + (size_t)l * D4 * DD, out_b + (size_t)l * DD,
            x /*residual*/, x, MM, DD, D4);
    }

    layernorm_kernel<<<MM, 256>>>(x, lnf_g, lnf_b, h, DD);

    // lm_head: logits = h @ wte^T   (NT GEMM, no bias)
    gemm_kernel<1, 0><<<dim3((VV + 63) / 64, MM / 64), tpb>>>(
        h, wte, nullptr, nullptr, logits, MM, VV, DD);
}

// round 2
// speedup vs baseline: 1.4937x; 1.4937x over previous
#include <cuda_runtime.h>
#include <cuda_bf16.h>
#include <math.h>

// ---------------- problem constants ----------------
#define BB   2
#define TT   1024
#define DD   768
#define HH   12
#define HDIM 64
#define LL   4
#define VV   50257
#define MM   (BB*TT)      // 2048 rows
#define D3   (3*DD)       // 2304
#define D4   (4*DD)       // 3072

// ---------------- scratch (device globals; no allocations allowed) ----------
__device__ float g_x   [MM * DD];   // residual stream
__device__ float g_h   [MM * DD];   // layernorm output
__device__ float g_qkv [MM * D3];   // qkv projection
__device__ float g_attn[MM * DD];   // attention output
__device__ float g_fc  [MM * D4];   // mlp hidden

// ---------------- helpers ----------------
__device__ __forceinline__ float to_tf32(float x) {
    unsigned u;
    asm("cvt.rna.tf32.f32 %0, %1;" : "=r"(u) : "f"(x));
    return __uint_as_float(u);
}

__device__ __forceinline__ void mma_tf32(float* c, const float* a, const float* b) {
    asm volatile(
        "mma.sync.aligned.m16n8k8.row.col.f32.tf32.tf32.f32 "
        "{%0,%1,%2,%3}, {%4,%5,%6,%7}, {%8,%9}, {%0,%1,%2,%3};"
        : "+f"(c[0]), "+f"(c[1]), "+f"(c[2]), "+f"(c[3])
        : "r"(__float_as_uint(a[0])), "r"(__float_as_uint(a[1])),
          "r"(__float_as_uint(a[2])), "r"(__float_as_uint(a[3])),
          "r"(__float_as_uint(b[0])), "r"(__float_as_uint(b[1])));
}

// ---------------- embedding ----------------
__global__ void embed_kernel(const int* __restrict__ ids,
                             const float* __restrict__ wte,
                             const float* __restrict__ wpe,
                             float* __restrict__ x) {
    int idx = blockIdx.x * blockDim.x + threadIdx.x;
    if (idx >= MM * DD) return;
    int d  = idx % DD;
    int bt = idx / DD;
    int t  = bt % TT;
    x[idx] = wte[(size_t)ids[bt] * DD + d] + wpe[(size_t)t * DD + d];
}

// ---------------- layernorm (one block per row) ----------------
__global__ void layernorm_kernel(const float* __restrict__ x,
                                 const float* __restrict__ g,
                                 const float* __restrict__ b,
                                 float* __restrict__ out, int D) {
    int row = blockIdx.x;
    int tid = threadIdx.x;
    __shared__ float red[256];
    __shared__ float s_mu, s_rstd;
    const float* xr = x + (size_t)row * D;

    float s = 0.f;
    for (int d = tid; d < D; d += 256) s += xr[d];
    red[tid] = s; __syncthreads();
    for (int o = 128; o > 0; o >>= 1) {
        if (tid < o) red[tid] += red[tid + o];
        __syncthreads();
    }
    if (tid == 0) s_mu = red[0] / D;
    __syncthreads();
    float mu = s_mu;

    float v = 0.f;
    for (int d = tid; d < D; d += 256) { float t = xr[d] - mu; v += t * t; }
    red[tid] = v; __syncthreads();
    for (int o = 128; o > 0; o >>= 1) {
        if (tid < o) red[tid] += red[tid + o];
        __syncthreads();
    }
    if (tid == 0) s_rstd = rsqrtf(red[0] / D + 1e-5f);
    __syncthreads();
    float rstd = s_rstd;

    float* orow = out + (size_t)row * D;
    for (int d = tid; d < D; d += 256)
        orow[d] = g[d] * (xr[d] - mu) * rstd + b[d];
}

// ---------------- tf32 tensor-core GEMM ----------------
// C[M,N] = A[M,K] @ B + bias (+gelu) (+residual)
// TRANS_B==0: B is [K,N] row-major (N must be multiple of 4).
// TRANS_B==1: B is [N,K] row-major (B^T applied), N-tail predicated.
// CTA tile 128x128, BK=32. 256 threads = 8 warps, warp tile 64(M)x32(N),
// mma.sync m16n8k8 tf32, register-prefetch pipelined smem.
// Requires: M % 128 == 0, K % 32 == 0.
template <int TRANS_B, int ACT>
__global__ void __launch_bounds__(256)
gemm_tc(const float* __restrict__ A, const float* __restrict__ B,
        const float* __restrict__ bias, const float* __restrict__ residual,
        float* __restrict__ C, int M, int N, int K) {
    __shared__ float As[128 * 36];   // [m][k], stride 36 (pad)
    __shared__ float Bs[32 * 132];   // [k][n], stride 132 (pad)

    const int tid  = threadIdx.x;
    const int lane = tid & 31;
    const int wid  = tid >> 5;
    const int wm   = (wid & 1) * 64;   // warp M offset within tile
    const int wn   = (wid >> 1) * 32;  // warp N offset within tile
    const int gp   = lane >> 2;        // group id 0..7
    const int tg   = lane & 3;         // thread-in-group 0..3
    const int row0 = blockIdx.y * 128;
    const int col0 = blockIdx.x * 128;

    // global-load mapping
    const int ar  = tid >> 3;          // A row 0..31 (+32*i)
    const int acx = (tid & 7) * 4;     // A col 0..28
    const int kbN = tid >> 5;          // normal-B k 0..7 (+8*i)
    const int nbN = (tid & 31) * 4;    // normal-B n
    const int nbT = tid >> 3;          // trans-B n 0..31 (+32*i)
    const int kbT = (tid & 7) * 4;     // trans-B k

    float acc[4][4][4];
#pragma unroll
    for (int a = 0; a < 4; a++)
#pragma unroll
        for (int b = 0; b < 4; b++)
#pragma unroll
            for (int c = 0; c < 4; c++) acc[a][b][c] = 0.f;

    float4 pa[4], pb[4];
    const int nk = K / 32;

    // ---- prefetch tile 0 ----
    {
        const float* Ab = A + (size_t)(row0 + ar) * K + acx;
#pragma unroll
        for (int i = 0; i < 4; i++)
            pa[i] = *reinterpret_cast<const float4*>(Ab + (size_t)(32 * i) * K);
        if (TRANS_B == 0) {
            const float* Bb = B + (size_t)kbN * N + col0 + nbN;
            bool ok = (col0 + nbN) < N;
#pragma unroll
            for (int i = 0; i < 4; i++)
                pb[i] = ok ? *reinterpret_cast<const float4*>(Bb + (size_t)(8 * i) * N)
                           : make_float4(0.f, 0.f, 0.f, 0.f);
        } else {
#pragma unroll
            for (int i = 0; i < 4; i++) {
                int n = nbT + 32 * i;
                pb[i] = (col0 + n < N)
                      ? *reinterpret_cast<const float4*>(B + (size_t)(col0 + n) * K + kbT)
                      : make_float4(0.f, 0.f, 0.f, 0.f);
            }
        }
    }

    for (int kt = 0; kt < nk; kt++) {
        // ---- store prefetched tile (with tf32 rounding) ----
#pragma unroll
        for (int i = 0; i < 4; i++) {
            float4 v = pa[i];
            float4 w = make_float4(to_tf32(v.x), to_tf32(v.y), to_tf32(v.z), to_tf32(v.w));
            *reinterpret_cast<float4*>(&As[(ar + 32 * i) * 36 + acx]) = w;
        }
        if (TRANS_B == 0) {
#pragma unroll
            for (int i = 0; i < 4; i++) {
                float4 v = pb[i];
                float4 w = make_float4(to_tf32(v.x), to_tf32(v.y), to_tf32(v.z), to_tf32(v.w));
                *reinterpret_cast<float4*>(&Bs[(kbN + 8 * i) * 132 + nbN]) = w;
            }
        } else {
#pragma unroll
            for (int i = 0; i < 4; i++) {
                float4 v = pb[i];
                int n = nbT + 32 * i;
                Bs[(kbT + 0) * 132 + n] = to_tf32(v.x);
                Bs[(kbT + 1) * 132 + n] = to_tf32(v.y);
                Bs[(kbT + 2) * 132 + n] = to_tf32(v.z);
                Bs[(kbT + 3) * 132 + n] = to_tf32(v.w);
            }
        }
        __syncthreads();

        // ---- prefetch next tile ----
        if (kt + 1 < nk) {
            int kt2 = (kt + 1) * 32;
            const float* Ab = A + (size_t)(row0 + ar) * K + kt2 + acx;
#pragma unroll
            for (int i = 0; i < 4; i++)
                pa[i] = *reinterpret_cast<const float4*>(Ab + (size_t)(32 * i) * K);
            if (TRANS_B == 0) {
                const float* Bb = B + (size_t)(kt2 + kbN) * N + col0 + nbN;
                bool ok = (col0 + nbN) < N;
#pragma unroll
                for (int i = 0; i < 4; i++)
                    pb[i] = ok ? *reinterpret_cast<const float4*>(Bb + (size_t)(8 * i) * N)
                               : make_float4(0.f, 0.f, 0.f, 0.f);
            } else {
#pragma unroll
                for (int i = 0; i < 4; i++) {
                    int n = nbT + 32 * i;
                    pb[i] = (col0 + n < N)
                          ? *reinterpret_cast<const float4*>(B + (size_t)(col0 + n) * K + kt2 + kbT)
                          : make_float4(0.f, 0.f, 0.f, 0.f);
                }
            }
        }

        // ---- compute from smem: 4 k-steps of 8 ----
#pragma unroll
        for (int ks = 0; ks < 4; ks++) {
            const int k = ks * 8;
            float afr[4][4], bfr[4][2];
#pragma unroll
            for (int mi = 0; mi < 4; mi++) {
                int r = wm + mi * 16 + gp;
                afr[mi][0] = As[r * 36 + k + tg];
                afr[mi][1] = As[(r + 8) * 36 + k + tg];
                afr[mi][2] = As[r * 36 + k + tg + 4];
                afr[mi][3] = As[(r + 8) * 36 + k + tg + 4];
            }
#pragma unroll
            for (int ni = 0; ni < 4; ni++) {
                int c = wn + ni * 8 + gp;
                bfr[ni][0] = Bs[(k + tg) * 132 + c];
                bfr[ni][1] = Bs[(k + tg + 4) * 132 + c];
            }
#pragma unroll
            for (int mi = 0; mi < 4; mi++)
#pragma unroll
                for (int ni = 0; ni < 4; ni++)
                    mma_tf32(acc[mi][ni], afr[mi], bfr[ni]);
        }
        __syncthreads();
    }

    // ---- epilogue ----
#pragma unroll
    for (int mi = 0; mi < 4; mi++) {
        int rbase = row0 + wm + mi * 16 + gp;
#pragma unroll
        for (int ni = 0; ni < 4; ni++) {
            int c = col0 + wn + ni * 8 + tg * 2;
#pragma unroll
            for (int half = 0; half < 2; half++) {
                int r = rbase + half * 8;
#pragma unroll
                for (int j = 0; j < 2; j++) {
                    int cc = c + j;
                    if (cc >= N) continue;
                    float v = acc[mi][ni][half * 2 + j];
                    if (bias) v += bias[cc];
                    if (ACT == 1)
                        v = 0.5f * v * (1.0f + erff(v * 0.70710678118654752f));
                    if (residual) v += residual[(size_t)r * N + cc];
                    C[(size_t)r * N + cc] = v;
                }
            }
        }
    }
}

// ---------------- attention: one block per (q, head, batch) ----------------
__global__ void attention_kernel(const float* __restrict__ qkv,
                                 float* __restrict__ out) {
    int q = blockIdx.x, h = blockIdx.y, b = blockIdx.z;
    int tid = threadIdx.x;
    __shared__ float sq[HDIM];
    __shared__ float ss[TT];
    __shared__ float red[256];

    const float* qptr = qkv + ((size_t)(b * TT + q)) * D3 + h * HDIM;
    if (tid < HDIM) sq[tid] = qptr[tid];
    __syncthreads();

    float lmax = -1e30f;
    for (int k = tid; k <= q; k += 256) {
        const float* kptr = qkv + ((size_t)(b * TT + k)) * D3 + DD + h * HDIM;
        float s = 0.f;
#pragma unroll
        for (int d = 0; d < HDIM; d++) s += sq[d] * kptr[d];
        s *= 0.125f;
        ss[k] = s;
        lmax = fmaxf(lmax, s);
    }
    red[tid] = lmax; __syncthreads();
    for (int o = 128; o > 0; o >>= 1) {
        if (tid < o) red[tid] = fmaxf(red[tid], red[tid + o]);
        __syncthreads();
    }
    float mx = red[0];
    __syncthreads();

    float lsum = 0.f;
    for (int k = tid; k <= q; k += 256) {
        float e = expf(ss[k] - mx);
        ss[k] = e;
        lsum += e;
    }
    red[tid] = lsum; __syncthreads();
    for (int o = 128; o > 0; o >>= 1) {
        if (tid < o) red[tid] += red[tid + o];
        __syncthreads();
    }
    float inv = 1.0f / red[0];

    if (tid < HDIM) {
        const float* vbase = qkv + (size_t)b * TT * D3 + 2 * DD + h * HDIM + tid;
        float acc = 0.f;
        for (int k = 0; k <= q; k++)
            acc += ss[k] * vbase[(size_t)k * D3];
        out[((size_t)(b * TT + q)) * DD + h * HDIM + tid] = acc * inv;
    }
}

// ---------------- launch ----------------
extern "C" void kernel_launch(void* const* d_in, const int* in_sizes, int n_in,
                              void* d_out, int out_size) {
    const int*   ids    = (const int*)  d_in[0];
    const float* wte    = (const float*)d_in[1];
    const float* wpe    = (const float*)d_in[2];
    const float* ln1_g  = (const float*)d_in[3];
    const float* ln1_b  = (const float*)d_in[4];
    const float* attn_w = (const float*)d_in[5];
    const float* attn_b = (const float*)d_in[6];
    const float* proj_w = (const float*)d_in[7];
    const float* proj_b = (const float*)d_in[8];
    const float* ln2_g  = (const float*)d_in[9];
    const float* ln2_b  = (const float*)d_in[10];
    const float* fc_w   = (const float*)d_in[11];
    const float* fc_b   = (const float*)d_in[12];
    const float* out_w  = (const float*)d_in[13];
    const float* out_b  = (const float*)d_in[14];
    const float* lnf_g  = (const float*)d_in[15];
    const float* lnf_b  = (const float*)d_in[16];
    float* logits = (float*)d_out;

    float *x, *h, *qkv, *attn, *fc;
    cudaGetSymbolAddress((void**)&x,    g_x);
    cudaGetSymbolAddress((void**)&h,    g_h);
    cudaGetSymbolAddress((void**)&qkv,  g_qkv);
    cudaGetSymbolAddress((void**)&attn, g_attn);
    cudaGetSymbolAddress((void**)&fc,   g_fc);

    embed_kernel<<<(MM * DD + 255) / 256, 256>>>(ids, wte, wpe, x);

    for (int l = 0; l < LL; l++) {
        // --- attention block ---
        layernorm_kernel<<<MM, 256>>>(x, ln1_g + l * DD, ln1_b + l * DD, h, DD);

        gemm_tc<0, 0><<<dim3(D3 / 128, MM / 128), 256>>>(
            h, attn_w + (size_t)l * DD * D3, attn_b + (size_t)l * D3,
            nullptr, qkv, MM, D3, DD);

        attention_kernel<<<dim3(TT, HH, BB), 256>>>(qkv, attn);

        gemm_tc<0, 0><<<dim3(DD / 128, MM / 128), 256>>>(
            attn, proj_w + (size_t)l * DD * DD, proj_b + (size_t)l * DD,
            x /*residual*/, x, MM, DD, DD);

        // --- mlp block ---
        layernorm_kernel<<<MM, 256>>>(x, ln2_g + l * DD, ln2_b + l * DD, h, DD);

        gemm_tc<0, 1><<<dim3(D4 / 128, MM / 128), 256>>>(
            h, fc_w + (size_t)l * DD * D4, fc_b + (size_t)l * D4,
            nullptr, fc, MM, D4, DD);

        gemm_tc<0, 0><<<dim3(DD / 128, MM / 128), 256>>>(
            fc, out_w + (size_t)l * D4 * DD, out_b + (size_t)l * DD,
            x /*residual*/, x, MM, DD, D4);
    }

    layernorm_kernel<<<MM, 256>>>(x, lnf_g, lnf_b, h, DD);

    // lm_head: logits = h @ wte^T   (NT GEMM, no bias)
    gemm_tc<1, 0><<<dim3((VV + 127) / 128, MM / 128), 256>>>(
        h, wte, nullptr, nullptr, logits, MM, VV, DD);
}